// round 2
// baseline (speedup 1.0000x reference)
#include <cuda_runtime.h>
#include <math.h>

#define HID   512
#define FOURH 2048
#define MID   256
#define CONDD 256
#define OPD   32
#define EXD   32
#define LLV   16
#define NN    1024
#define TT    8
#define BB    (LLV*NN)   /* 16384 */

typedef unsigned long long ull;

// ------------------------- scratch (device globals; no allocs) -------------
__device__ __align__(16) float  g_h1[BB*HID];
__device__ __align__(16) float  g_c1[BB*HID];
__device__ __align__(16) float  g_gates[(size_t)BB*FOURH];
__device__ __align__(16) float  g_last[BB*MID];
__device__ __align__(16) float  g_xp2[(size_t)LLV*NN*FOURH];
__device__ __align__(16) float  g_h2[NN*HID];
__device__ __align__(16) float  g_c2[NN*HID];
__device__ __align__(16) float  g_hb[NN*HID];
__device__ __align__(16) float  g_cb[NN*HID];
__device__ __align__(16) float  g_gates2[NN*FOURH];
__device__ double g_bnacc[2*HID];
__device__ float  g_mu[HID];
__device__ float  g_rs[HID];
__device__ int    g_map64;

// ------------------------- f32x2 helpers -----------------------------------
__device__ __forceinline__ ull dup_f(float a) {
    ull r; unsigned u = __float_as_uint(a);
    asm("mov.b64 %0, {%1, %1};" : "=l"(r) : "r"(u));
    return r;
}
__device__ __forceinline__ void ffma2(ull& d, ull a, ull b) {
    asm("fma.rn.f32x2 %0, %1, %2, %0;" : "+l"(d) : "l"(a), "l"(b));
}
__device__ __forceinline__ float2 unp(ull v) {
    unsigned lo, hi;
    asm("mov.b64 {%0, %1}, %2;" : "=r"(lo), "=r"(hi) : "l"(v));
    float2 f; f.x = __uint_as_float(lo); f.y = __uint_as_float(hi);
    return f;
}

// ------------------------- GEMM --------------------------------------------
// C[m,n] = sum_k A[m,k]*B[n,k] (+epilogue). A and B may be split into K-segments
// (concat inputs / concat weights). All M,N multiples of 128; K multiple of 32;
// every segment boundary is a multiple of 32, so each K-tile lies in one segment.
// MODE 0: +bias0+bias1 (lstm1 gates)     MODE 1: relu(+bias0) (cond linear)
// MODE 2: +bias0 (xp2)                   MODE 3: +bias0+Cadd   (tree gates)
#define BM 128
#define BN 128
#define BK 32
#define LDS_ 132

template<int MODE>
__global__ __launch_bounds__(256, 2)
void gemm_k(const float* __restrict__ A0, int sA0, int kA1,
            const float* __restrict__ A1, int sA1, int kA2,
            const float* __restrict__ A2, int sA2,
            const float* __restrict__ B0, int sB0, int kB1,
            const float* __restrict__ B1, int sB1,
            const float* __restrict__ bias0, const float* __restrict__ bias1,
            const float* __restrict__ Cadd,
            float* __restrict__ C, int N, int K)
{
    __shared__ __align__(16) float As[BK][LDS_];
    __shared__ __align__(16) float Bs[BK][LDS_];
    int tid = threadIdx.x;
    int mBase = blockIdx.y * BM;
    int nBase = blockIdx.x * BN;
    int lr = tid >> 3;            // 0..31
    int lk = (tid & 7) << 2;      // 0,4,..,28
    int tx = tid & 15, ty = tid >> 4;
    int m0 = ty << 3, n0 = tx << 3;

    ull acc[8][4];
#pragma unroll
    for (int i = 0; i < 8; i++)
#pragma unroll
        for (int j = 0; j < 4; j++) acc[i][j] = 0ULL;

    for (int k0 = 0; k0 < K; k0 += BK) {
        const float* ap; int as_;
        if (k0 < kA1)      { ap = A0 + k0;         as_ = sA0; }
        else if (k0 < kA2) { ap = A1 + (k0 - kA1); as_ = sA1; }
        else               { ap = A2 + (k0 - kA2); as_ = sA2; }
        const float* bp; int bs_;
        if (k0 < kB1) { bp = B0 + k0;          bs_ = sB0; }
        else          { bp = B1 + (k0 - kB1);  bs_ = sB1; }

#pragma unroll
        for (int i = 0; i < 4; i++) {
            int r = lr + (i << 5);
            float4 va = *(const float4*)(ap + (long)(mBase + r) * as_ + lk);
            As[lk+0][r] = va.x; As[lk+1][r] = va.y; As[lk+2][r] = va.z; As[lk+3][r] = va.w;
            float4 vb = *(const float4*)(bp + (long)(nBase + r) * bs_ + lk);
            Bs[lk+0][r] = vb.x; Bs[lk+1][r] = vb.y; Bs[lk+2][r] = vb.z; Bs[lk+3][r] = vb.w;
        }
        __syncthreads();

#pragma unroll 4
        for (int k = 0; k < BK; k++) {
            float4 a0 = *(const float4*)&As[k][m0];
            float4 a1 = *(const float4*)&As[k][m0+4];
            ulonglong2 b0 = *(const ulonglong2*)&Bs[k][n0];
            ulonglong2 b1 = *(const ulonglong2*)&Bs[k][n0+4];
            ull ad[8];
            ad[0]=dup_f(a0.x); ad[1]=dup_f(a0.y); ad[2]=dup_f(a0.z); ad[3]=dup_f(a0.w);
            ad[4]=dup_f(a1.x); ad[5]=dup_f(a1.y); ad[6]=dup_f(a1.z); ad[7]=dup_f(a1.w);
#pragma unroll
            for (int i = 0; i < 8; i++) {
                ffma2(acc[i][0], ad[i], b0.x);
                ffma2(acc[i][1], ad[i], b0.y);
                ffma2(acc[i][2], ad[i], b1.x);
                ffma2(acc[i][3], ad[i], b1.y);
            }
        }
        __syncthreads();
    }

#pragma unroll
    for (int i = 0; i < 8; i++) {
        long gm = mBase + m0 + i;
#pragma unroll
        for (int jp = 0; jp < 4; jp++) {
            int gn = nBase + n0 + (jp << 1);
            float2 v = unp(acc[i][jp]);
            if (MODE == 0) {
                v.x += bias0[gn]   + bias1[gn];
                v.y += bias0[gn+1] + bias1[gn+1];
            } else if (MODE == 1) {
                v.x = fmaxf(v.x + bias0[gn],   0.f);
                v.y = fmaxf(v.y + bias0[gn+1], 0.f);
            } else if (MODE == 2) {
                v.x += bias0[gn];
                v.y += bias0[gn+1];
            } else {
                v.x += bias0[gn]   + Cadd[gm*N + gn];
                v.y += bias0[gn+1] + Cadd[gm*N + gn+1];
            }
            *(float2*)&C[gm*N + gn] = v;
        }
    }
}

// ------------------------- elementwise kernels -----------------------------
__device__ __forceinline__ float sigm(float x) { return 1.f/(1.f + expf(-x)); }

__global__ void cell_k(const float* __restrict__ gates, const float* __restrict__ cin,
                       float* __restrict__ h, float* __restrict__ c, int total)
{
    int idx = blockIdx.x*blockDim.x + threadIdx.x;
    if (idx >= total) return;
    int m = idx >> 9, j = idx & 511;
    const float* g = gates + (long)m*FOURH;
    float i_ = sigm(g[j]);
    float f_ = sigm(g[HID + j]);
    float gg = tanhf(g[2*HID + j]);
    float o_ = sigm(g[3*HID + j]);
    float cc = f_*cin[idx] + i_*gg;
    c[idx] = cc;
    h[idx] = o_*tanhf(cc);
}

__global__ void tcell0_k(const float* __restrict__ xpl, const float* __restrict__ bhh,
                         float* __restrict__ h, float* __restrict__ c)
{
    int idx = blockIdx.x*blockDim.x + threadIdx.x;  // NN*HID threads
    int m = idx >> 9, j = idx & 511;
    const float* g = xpl + (long)m*FOURH;
    float i_ = sigm(g[j] + bhh[j]);
    float gg = tanhf(g[2*HID + j] + bhh[2*HID + j]);
    float o_ = sigm(g[3*HID + j] + bhh[3*HID + j]);
    float cc = i_*gg;
    c[idx] = cc;
    h[idx] = o_*tanhf(cc);
}

__global__ void detect_k(const int* __restrict__ m32)
{
    if (threadIdx.x == 0 && blockIdx.x == 0) {
        int all0 = 1;
        for (int i = 1; i < 64; i += 2) all0 &= (m32[i] == 0);
        g_map64 = all0;   // int64 mapping (values<=1024 -> high words all zero)
    }
}

__global__ void gather_k(const void* __restrict__ mapping, int level,
                         const float* __restrict__ h, const float* __restrict__ c,
                         float* __restrict__ hb, float* __restrict__ cb)
{
    int idx = blockIdx.x*blockDim.x + threadIdx.x;  // NN*HID
    int n = idx >> 9, j = idx & 511;
    long flat = ((long)level*NN + n)*2;
    int m0, m1;
    if (g_map64) {
        m0 = (int)((const long long*)mapping)[flat];
        m1 = (int)((const long long*)mapping)[flat+1];
    } else {
        m0 = ((const int*)mapping)[flat];
        m1 = ((const int*)mapping)[flat+1];
    }
    float hv = 0.f, cv = 0.f;
    if (m0 > 0) { hv += h[(long)(m0-1)*HID + j]; cv += c[(long)(m0-1)*HID + j]; }
    if (m1 > 0) { hv += h[(long)(m1-1)*HID + j]; cv += c[(long)(m1-1)*HID + j]; }
    hb[idx] = 0.5f*hv;
    cb[idx] = 0.5f*cv;
}

// ------------------------- batchnorm ---------------------------------------
__global__ void bn_part_k(const float* __restrict__ x, int M, int N, double* __restrict__ acc)
{
    int rows = (M + gridDim.x - 1)/gridDim.x;
    int r0 = blockIdx.x * rows;
    int r1 = min(M, r0 + rows);
    for (int col = threadIdx.x; col < N; col += blockDim.x) {
        double s = 0.0, s2 = 0.0;
        for (int r = r0; r < r1; r++) {
            float v = x[(long)r*N + col];
            s += v; s2 += (double)v*v;
        }
        atomicAdd(&acc[col], s);
        atomicAdd(&acc[N + col], s2);
    }
}

__global__ void bn_fin_k(const double* __restrict__ acc, int M, int N,
                         float* __restrict__ mu, float* __restrict__ rs)
{
    int j = blockIdx.x*blockDim.x + threadIdx.x;
    if (j < N) {
        double m = acc[j]/M;
        double var = acc[N + j]/M - m*m;
        mu[j] = (float)m;
        rs[j] = rsqrtf((float)var + 1e-5f);
    }
}

__global__ void bn_apply_k(const float* __restrict__ x, const float* __restrict__ mu,
                           const float* __restrict__ rs, const float* __restrict__ gm,
                           const float* __restrict__ bt, float* __restrict__ y, int M, int N)
{
    int idx = blockIdx.x*blockDim.x + threadIdx.x;
    if (idx < M*N) {
        int j = idx % N;
        y[idx] = gm[j]*(x[idx] - mu[j])*rs[j] + bt[j];
    }
}

// ------------------------- orchestration -----------------------------------
extern "C" void kernel_launch(void* const* d_in, const int* in_sizes, int n_in,
                              void* d_out, int out_size)
{
    const float* operators = (const float*)d_in[0];
    const float* extras    = (const float*)d_in[1];
    const float* conds     = (const float*)d_in[2];
    const void*  mapping   =               d_in[4];
    const float* w1ih = (const float*)d_in[5];
    const float* w1hh = (const float*)d_in[6];
    const float* b1ih = (const float*)d_in[7];
    const float* b1hh = (const float*)d_in[8];
    const float* condW = (const float*)d_in[9];
    const float* condb = (const float*)d_in[10];
    const float* bn1g = (const float*)d_in[11];
    const float* bn1b = (const float*)d_in[12];
    const float* w2ih = (const float*)d_in[13];
    const float* w2hh = (const float*)d_in[14];
    const float* b2ih = (const float*)d_in[15];
    const float* b2hh = (const float*)d_in[16];
    const float* bn2g = (const float*)d_in[17];
    const float* bn2b = (const float*)d_in[18];
    float* out = (float*)d_out;

    float *h1, *c1, *gates, *last, *xp2, *h2, *c2, *hb, *cb, *gates2, *mu, *rs;
    double* bnacc;
    cudaGetSymbolAddress((void**)&h1,     g_h1);
    cudaGetSymbolAddress((void**)&c1,     g_c1);
    cudaGetSymbolAddress((void**)&gates,  g_gates);
    cudaGetSymbolAddress((void**)&last,   g_last);
    cudaGetSymbolAddress((void**)&xp2,    g_xp2);
    cudaGetSymbolAddress((void**)&h2,     g_h2);
    cudaGetSymbolAddress((void**)&c2,     g_c2);
    cudaGetSymbolAddress((void**)&hb,     g_hb);
    cudaGetSymbolAddress((void**)&cb,     g_cb);
    cudaGetSymbolAddress((void**)&gates2, g_gates2);
    cudaGetSymbolAddress((void**)&bnacc,  g_bnacc);
    cudaGetSymbolAddress((void**)&mu,     g_mu);
    cudaGetSymbolAddress((void**)&rs,     g_rs);

    cudaMemsetAsync(h1, 0, sizeof(float)*(size_t)BB*HID);
    cudaMemsetAsync(c1, 0, sizeof(float)*(size_t)BB*HID);
    detect_k<<<1, 32>>>((const int*)mapping);

    dim3 blk(256);

    // ---- lstm1: 8 fused steps: gates = [x_t | h] @ [W1ih | W1hh]^T + b1ih + b1hh
    for (int t = 0; t < TT; t++) {
        gemm_k<0><<<dim3(FOURH/BN, BB/BM), blk>>>(
            conds + t*CONDD, TT*CONDD, CONDD,
            h1, HID, CONDD + HID,
            (const float*)0, 0,
            w1ih, CONDD, CONDD, w1hh, HID,
            b1ih, b1hh, (const float*)0,
            gates, FOURH, CONDD + HID);
        cell_k<<<(BB*HID)/256, blk>>>(gates, c1, h1, c1, BB*HID);
    }

    // ---- last = relu(h1 @ condW^T + condb)
    gemm_k<1><<<dim3(MID/BN, BB/BM), blk>>>(
        h1, HID, HID, (const float*)0, 0, HID, (const float*)0, 0,
        condW, HID, HID, (const float*)0, 0,
        condb, (const float*)0, (const float*)0,
        last, MID, HID);

    // ---- batchnorm1 (in place)
    cudaMemsetAsync(bnacc, 0, sizeof(double)*2*MID);
    bn_part_k<<<64, 256>>>(last, BB, MID, bnacc);
    bn_fin_k<<<2, 256>>>(bnacc, BB, MID, mu, rs);
    bn_apply_k<<<(BB*MID)/256, 256>>>(last, mu, rs, bn1g, bn1b, last, BB, MID);

    // ---- xp2 = [op | extra | last] @ W2ih^T + b2ih   (all 16 levels at once)
    gemm_k<2><<<dim3(FOURH/BN, BB/BM), blk>>>(
        operators, OPD, OPD,
        extras, EXD, OPD + EXD,
        last, MID,
        w2ih, OPD + EXD + MID, OPD + EXD + MID, (const float*)0, 0,
        b2ih, (const float*)0, (const float*)0,
        xp2, FOURH, OPD + EXD + MID);

    // ---- tree LSTM: init from level L-1 with h=c=0
    tcell0_k<<<(NN*HID)/256, 256>>>(xp2 + (long)(LLV-1)*NN*FOURH, b2hh, h2, c2);

    for (int lvl = LLV - 2; lvl >= 0; lvl--) {
        gather_k<<<(NN*HID)/256, 256>>>(mapping, lvl, h2, c2, hb, cb);
        gemm_k<3><<<dim3(FOURH/BN, NN/BM), blk>>>(
            hb, HID, HID, (const float*)0, 0, HID, (const float*)0, 0,
            w2hh, HID, HID, (const float*)0, 0,
            b2hh, (const float*)0, xp2 + (long)lvl*NN*FOURH,
            gates2, FOURH, HID);
        cell_k<<<(NN*HID)/256, blk>>>(gates2, cb, h2, c2, NN*HID);
    }

    // ---- batchnorm2 -> output
    cudaMemsetAsync(bnacc, 0, sizeof(double)*2*HID);
    bn_part_k<<<16, 256>>>(h2, NN, HID, bnacc);
    bn_fin_k<<<2, 256>>>(bnacc, NN, HID, mu, rs);
    bn_apply_k<<<(NN*HID)/256, 256>>>(h2, mu, rs, bn2g, bn2b, out, NN, HID);
}

// round 4
// speedup vs baseline: 1.4149x; 1.4149x over previous
#include <cuda_runtime.h>
#include <cuda_bf16.h>
#include <math.h>
#include <stdint.h>

typedef unsigned long long ull;
typedef __nv_bfloat16 bf16;

#define HID   512
#define FOURH 2048
#define MID   256
#define CONDD 256
#define OPD   32
#define EXD   32
#define LLV   16
#define NN    1024
#define TT    8
#define BB    (LLV*NN)   /* 16384 */

// ---------------------------------------------------------------- scratch ---
__device__ __align__(16) bf16  g_condh[(size_t)BB*2048];
__device__ __align__(16) bf16  g_condl[(size_t)BB*2048];
__device__ __align__(16) bf16  g_h1h[(size_t)BB*HID];
__device__ __align__(16) bf16  g_h1l[(size_t)BB*HID];
__device__ __align__(16) float g_c1[(size_t)BB*HID];
__device__ __align__(16) float g_gates[(size_t)BB*FOURH];
__device__ __align__(16) float g_last[(size_t)BB*MID];
__device__ __align__(16) bf16  g_lasth[(size_t)BB*MID];
__device__ __align__(16) bf16  g_lastl[(size_t)BB*MID];
__device__ __align__(16) bf16  g_opexh[(size_t)BB*64];
__device__ __align__(16) bf16  g_opexl[(size_t)BB*64];
__device__ __align__(16) float g_xp2[(size_t)BB*FOURH];
__device__ __align__(16) float g_h2[NN*HID];
__device__ __align__(16) float g_c2[NN*HID];
__device__ __align__(16) bf16  g_hbh[NN*HID];
__device__ __align__(16) bf16  g_hbl[NN*HID];
__device__ __align__(16) float g_cb[NN*HID];
__device__ __align__(16) float g_gates2[NN*FOURH];
__device__ __align__(16) bf16  g_w1h[FOURH*768];
__device__ __align__(16) bf16  g_w1l[FOURH*768];
__device__ __align__(16) bf16  g_cwh[MID*HID];
__device__ __align__(16) bf16  g_cwl[MID*HID];
__device__ __align__(16) bf16  g_w2ih[FOURH*320];
__device__ __align__(16) bf16  g_w2il[FOURH*320];
__device__ __align__(16) bf16  g_w2hh[FOURH*HID];
__device__ __align__(16) bf16  g_w2hl[FOURH*HID];
__device__ double g_bnacc[2*HID];
__device__ float  g_mu[HID];
__device__ float  g_rs[HID];
__device__ int    g_map64;

// ---------------------------------------------------------------- helpers ---
__device__ __forceinline__ uint32_t smem_u32(const void* p) {
    uint32_t a;
    asm("{ .reg .u64 t; cvta.to.shared.u64 t, %1; cvt.u32.u64 %0, t; }" : "=r"(a) : "l"(p));
    return a;
}
__device__ __forceinline__ void cpa16(uint32_t dst, const void* src) {
    asm volatile("cp.async.cg.shared.global [%0], [%1], 16;" :: "r"(dst), "l"(src) : "memory");
}
__device__ __forceinline__ void ldmx4(uint32_t* r, uint32_t addr) {
    asm volatile("ldmatrix.sync.aligned.m8n8.x4.shared.b16 {%0,%1,%2,%3}, [%4];"
        : "=r"(r[0]), "=r"(r[1]), "=r"(r[2]), "=r"(r[3]) : "r"(addr));
}
__device__ __forceinline__ void mma_bf16(float* d, const uint32_t* a, const uint32_t* b) {
    asm volatile("mma.sync.aligned.m16n8k16.row.col.f32.bf16.bf16.f32 "
        "{%0,%1,%2,%3}, {%4,%5,%6,%7}, {%8,%9}, {%0,%1,%2,%3};"
        : "+f"(d[0]), "+f"(d[1]), "+f"(d[2]), "+f"(d[3])
        : "r"(a[0]), "r"(a[1]), "r"(a[2]), "r"(a[3]), "r"(b[0]), "r"(b[1]));
}

// ---------------------------------------------------------------- GEMM ------
// C[M,Nf] = A[M,K] @ B[Nf,K]^T via split-bf16 (3 mma products).
// CTA tile 128x128, K-chunks of 32, double-buffered cp.async.
// Smem rows padded to 80B (stride-5 of 16B banks => conflict-free ldmatrix).
// A has up to 2 K-segments (boundary multiple of 32). B contiguous [Nf][K].
// MODE 0: +bias0+bias1 | 1: relu(+bias0) | 2: +bias0 | 3: +bias0+Cadd
#define T_AH 0
#define T_AL 10240
#define T_BH 20480
#define T_BL 30720
#define STAGE 40960
#define SMEM_TOT (2*STAGE)

template<int MODE>
__global__ __launch_bounds__(256, 1)
void gemm_tc(const bf16* __restrict__ A0h, const bf16* __restrict__ A0l, long sA0, int kSplit,
             const bf16* __restrict__ A1h, const bf16* __restrict__ A1l, long sA1,
             const bf16* __restrict__ Bh,  const bf16* __restrict__ Bl,
             const float* __restrict__ bias0, const float* __restrict__ bias1,
             const float* __restrict__ Cadd,
             float* __restrict__ C, int Nf, int K)
{
    extern __shared__ __align__(128) char sm[];
    uint32_t smb = smem_u32(sm);
    int tid = threadIdx.x;
    int mBase = blockIdx.y * 128;
    int nBase = blockIdx.x * 128;

    float acc[4][4][4];
#pragma unroll
    for (int a = 0; a < 4; a++)
#pragma unroll
        for (int b = 0; b < 4; b++)
#pragma unroll
            for (int q = 0; q < 4; q++) acc[a][b][q] = 0.f;

    int NC = K >> 5;

    auto issue_stage = [&](int s, int c) {
        int kc = c << 5;
        const bf16 *ah, *al; long sA; int col;
        if (kc < kSplit) { ah = A0h; al = A0l; sA = sA0; col = kc; }
        else             { ah = A1h; al = A1l; sA = sA1; col = kc - kSplit; }
        uint32_t stg = smb + (uint32_t)s * STAGE;
#pragma unroll
        for (int i = 0; i < 2; i++) {
            int idx = tid + (i << 8);
            int row = idx >> 2, cc = idx & 3;
            long eo = (long)(mBase + row) * sA + col + (cc << 3);
            uint32_t d = stg + row * 80 + cc * 16;
            cpa16(d + T_AH, ah + eo);
            cpa16(d + T_AL, al + eo);
        }
#pragma unroll
        for (int i = 0; i < 2; i++) {
            int idx = tid + (i << 8);
            int row = idx >> 2, cc = idx & 3;
            long eo = (long)(nBase + row) * (long)K + kc + (cc << 3);
            uint32_t d = stg + row * 80 + cc * 16;
            cpa16(d + T_BH, Bh + eo);
            cpa16(d + T_BL, Bl + eo);
        }
        asm volatile("cp.async.commit_group;" ::: "memory");
    };

    int lane = tid & 31, wid = tid >> 5;
    int wm = wid & 1, wn = wid >> 1;
    int arow = (lane & 7) + (((lane >> 3) & 1) << 3);
    int ahalf = lane >> 4;
    int brow = ((lane >> 4) << 3) + (lane & 7);
    int bhalf = (lane >> 3) & 1;

    issue_stage(0, 0);
    for (int c = 0; c < NC; c++) {
        if (c + 1 < NC) {
            issue_stage((c + 1) & 1, c + 1);
            asm volatile("cp.async.wait_group 1;" ::: "memory");
        } else {
            asm volatile("cp.async.wait_group 0;" ::: "memory");
        }
        __syncthreads();

        uint32_t sb = smb + (uint32_t)(c & 1) * STAGE;
#pragma unroll
        for (int ks = 0; ks < 2; ks++) {
            uint32_t a_h[4][4], a_l[4][4], b_h[4][2], b_l[4][2];
#pragma unroll
            for (int mt = 0; mt < 4; mt++) {
                uint32_t ad = sb + T_AH + (uint32_t)(wm * 64 + mt * 16 + arow) * 80
                            + (uint32_t)(ks * 2 + ahalf) * 16;
                ldmx4(a_h[mt], ad);
                ldmx4(a_l[mt], ad + (T_AL - T_AH));
            }
#pragma unroll
            for (int bp = 0; bp < 2; bp++) {
                uint32_t bd = sb + T_BH + (uint32_t)(wn * 32 + bp * 16 + brow) * 80
                            + (uint32_t)(ks * 2 + bhalf) * 16;
                ldmx4(&b_h[bp * 2][0], bd);
                ldmx4(&b_l[bp * 2][0], bd + (T_BL - T_BH));
            }
#pragma unroll
            for (int mt = 0; mt < 4; mt++)
#pragma unroll
                for (int nt = 0; nt < 4; nt++) {
                    mma_bf16(acc[mt][nt], a_h[mt], b_h[nt]);
                    mma_bf16(acc[mt][nt], a_h[mt], b_l[nt]);
                    mma_bf16(acc[mt][nt], a_l[mt], b_h[nt]);
                }
        }
        __syncthreads();
    }

    // ---- epilogue
    int r4 = lane >> 2, c2 = (lane & 3) << 1;
#pragma unroll
    for (int mt = 0; mt < 4; mt++) {
        long m0 = mBase + wm * 64 + mt * 16 + r4;
#pragma unroll
        for (int nt = 0; nt < 4; nt++) {
            int gn = nBase + wn * 32 + nt * 8 + c2;
#pragma unroll
            for (int half = 0; half < 2; half++) {
                long gm = m0 + half * 8;
                float vx = acc[mt][nt][half * 2 + 0];
                float vy = acc[mt][nt][half * 2 + 1];
                if (MODE == 0) {
                    vx += bias0[gn]     + bias1[gn];
                    vy += bias0[gn + 1] + bias1[gn + 1];
                } else if (MODE == 1) {
                    vx = fmaxf(vx + bias0[gn],     0.f);
                    vy = fmaxf(vy + bias0[gn + 1], 0.f);
                } else if (MODE == 2) {
                    vx += bias0[gn];
                    vy += bias0[gn + 1];
                } else {
                    vx += bias0[gn]     + Cadd[gm * (long)Nf + gn];
                    vy += bias0[gn + 1] + Cadd[gm * (long)Nf + gn + 1];
                }
                float2 v; v.x = vx; v.y = vy;
                *(float2*)&C[gm * (long)Nf + gn] = v;
            }
        }
    }
}

// ----------------------------------------------------------- elementwise ----
__device__ __forceinline__ float sigm(float x) { return 1.f / (1.f + expf(-x)); }
__device__ __forceinline__ void splitw(float v, bf16& h, bf16& l) {
    h = __float2bfloat16(v);
    l = __float2bfloat16(v - __bfloat162float(h));
}

__global__ void split_k(const float* __restrict__ src, long sStr, int cols,
                        bf16* __restrict__ dh, bf16* __restrict__ dl,
                        long dStr, int dOff, long total)
{
    long idx = (long)blockIdx.x * blockDim.x + threadIdx.x;
    if (idx >= total) return;
    long r = idx / cols; int cc = (int)(idx - r * cols);
    float v = src[r * sStr + cc];
    bf16 h, l; splitw(v, h, l);
    dh[r * dStr + dOff + cc] = h;
    dl[r * dStr + dOff + cc] = l;
}

__global__ void cell1_k(const float* __restrict__ g, const float* __restrict__ cin,
                        bf16* __restrict__ hh, bf16* __restrict__ hl, float* __restrict__ co)
{
    long idx = (long)blockIdx.x * blockDim.x + threadIdx.x;
    long m = idx >> 9; int j = idx & 511;
    const float* gr = g + m * FOURH;
    float i_ = sigm(gr[j]);
    float f_ = sigm(gr[HID + j]);
    float gg = tanhf(gr[2*HID + j]);
    float o_ = sigm(gr[3*HID + j]);
    float cc = f_ * cin[idx] + i_ * gg;
    co[idx] = cc;
    float h = o_ * tanhf(cc);
    bf16 hb, lb; splitw(h, hb, lb);
    hh[idx] = hb; hl[idx] = lb;
}

__global__ void cellT_k(const float* __restrict__ g, const float* __restrict__ cin,
                        float* __restrict__ h, float* __restrict__ c)
{
    int idx = blockIdx.x * blockDim.x + threadIdx.x;
    int m = idx >> 9, j = idx & 511;
    const float* gr = g + (long)m * FOURH;
    float i_ = sigm(gr[j]);
    float f_ = sigm(gr[HID + j]);
    float gg = tanhf(gr[2*HID + j]);
    float o_ = sigm(gr[3*HID + j]);
    float cc = f_ * cin[idx] + i_ * gg;
    c[idx] = cc;
    h[idx] = o_ * tanhf(cc);
}

__global__ void tcell0_k(const float* __restrict__ xpl, const float* __restrict__ bhh,
                         float* __restrict__ h, float* __restrict__ c)
{
    int idx = blockIdx.x * blockDim.x + threadIdx.x;
    int m = idx >> 9, j = idx & 511;
    const float* g = xpl + (long)m * FOURH;
    float i_ = sigm(g[j] + bhh[j]);
    float gg = tanhf(g[2*HID + j] + bhh[2*HID + j]);
    float o_ = sigm(g[3*HID + j] + bhh[3*HID + j]);
    float cc = i_ * gg;
    c[idx] = cc;
    h[idx] = o_ * tanhf(cc);
}

__global__ void detect_k(const int* __restrict__ m32)
{
    if (threadIdx.x == 0 && blockIdx.x == 0) {
        int all0 = 1;
        for (int i = 1; i < 64; i += 2) all0 &= (m32[i] == 0);
        g_map64 = all0;
    }
}

__global__ void gatherT_k(const void* __restrict__ mapping, int level,
                          const float* __restrict__ h, const float* __restrict__ c,
                          bf16* __restrict__ hbh, bf16* __restrict__ hbl, float* __restrict__ cb)
{
    int idx = blockIdx.x * blockDim.x + threadIdx.x;
    int n = idx >> 9, j = idx & 511;
    long flat = ((long)level * NN + n) * 2;
    int m0, m1;
    if (g_map64) {
        m0 = (int)((const long long*)mapping)[flat];
        m1 = (int)((const long long*)mapping)[flat + 1];
    } else {
        m0 = ((const int*)mapping)[flat];
        m1 = ((const int*)mapping)[flat + 1];
    }
    float hv = 0.f, cv = 0.f;
    if (m0 > 0) { hv += h[(long)(m0-1)*HID + j]; cv += c[(long)(m0-1)*HID + j]; }
    if (m1 > 0) { hv += h[(long)(m1-1)*HID + j]; cv += c[(long)(m1-1)*HID + j]; }
    hv *= 0.5f; cv *= 0.5f;
    bf16 hb, lb; splitw(hv, hb, lb);
    hbh[idx] = hb; hbl[idx] = lb;
    cb[idx] = cv;
}

// ---------------------------------------------------------------- batchnorm -
__global__ void bn_part_k(const float* __restrict__ x, int M, int N, double* __restrict__ acc)
{
    int rows = (M + gridDim.x - 1) / gridDim.x;
    int r0 = blockIdx.x * rows;
    int r1 = min(M, r0 + rows);
    for (int col = threadIdx.x; col < N; col += blockDim.x) {
        double s = 0.0, s2 = 0.0;
        for (int r = r0; r < r1; r++) {
            float v = x[(long)r * N + col];
            s += v; s2 += (double)v * v;
        }
        atomicAdd(&acc[col], s);
        atomicAdd(&acc[N + col], s2);
    }
}

__global__ void bn_fin_k(const double* __restrict__ acc, int M, int N,
                         float* __restrict__ mu, float* __restrict__ rs)
{
    int j = blockIdx.x * blockDim.x + threadIdx.x;
    if (j < N) {
        double m = acc[j] / M;
        double var = acc[N + j] / M - m * m;
        mu[j] = (float)m;
        rs[j] = rsqrtf((float)var + 1e-5f);
    }
}

__global__ void bn_apply_split_k(const float* __restrict__ x, const float* __restrict__ mu,
                                 const float* __restrict__ rs, const float* __restrict__ gm_,
                                 const float* __restrict__ bt,
                                 bf16* __restrict__ dh, bf16* __restrict__ dl, int M, int N)
{
    long idx = (long)blockIdx.x * blockDim.x + threadIdx.x;
    if (idx < (long)M * N) {
        int j = idx % N;
        float v = gm_[j] * (x[idx] - mu[j]) * rs[j] + bt[j];
        bf16 h, l; splitw(v, h, l);
        dh[idx] = h; dl[idx] = l;
    }
}

__global__ void bn_apply_k(const float* __restrict__ x, const float* __restrict__ mu,
                           const float* __restrict__ rs, const float* __restrict__ gm_,
                           const float* __restrict__ bt, float* __restrict__ y, int M, int N)
{
    int idx = blockIdx.x * blockDim.x + threadIdx.x;
    if (idx < M * N) {
        int j = idx % N;
        y[idx] = gm_[j] * (x[idx] - mu[j]) * rs[j] + bt[j];
    }
}

// ------------------------------------------------------------ orchestration -
extern "C" void kernel_launch(void* const* d_in, const int* in_sizes, int n_in,
                              void* d_out, int out_size)
{
    const float* operators = (const float*)d_in[0];
    const float* extras    = (const float*)d_in[1];
    const float* conds     = (const float*)d_in[2];
    const void*  mapping   =               d_in[4];
    const float* w1ih = (const float*)d_in[5];
    const float* w1hh = (const float*)d_in[6];
    const float* b1ih = (const float*)d_in[7];
    const float* b1hh = (const float*)d_in[8];
    const float* condW = (const float*)d_in[9];
    const float* condb = (const float*)d_in[10];
    const float* bn1g = (const float*)d_in[11];
    const float* bn1b = (const float*)d_in[12];
    const float* w2ih = (const float*)d_in[13];
    const float* w2hh = (const float*)d_in[14];
    const float* b2ih = (const float*)d_in[15];
    const float* b2hh = (const float*)d_in[16];
    const float* bn2g = (const float*)d_in[17];
    const float* bn2b = (const float*)d_in[18];
    float* out = (float*)d_out;

    cudaFuncSetAttribute(gemm_tc<0>, cudaFuncAttributeMaxDynamicSharedMemorySize, SMEM_TOT);
    cudaFuncSetAttribute(gemm_tc<1>, cudaFuncAttributeMaxDynamicSharedMemorySize, SMEM_TOT);
    cudaFuncSetAttribute(gemm_tc<2>, cudaFuncAttributeMaxDynamicSharedMemorySize, SMEM_TOT);
    cudaFuncSetAttribute(gemm_tc<3>, cudaFuncAttributeMaxDynamicSharedMemorySize, SMEM_TOT);

    bf16 *condh, *condl, *h1h, *h1l, *lasth, *lastl, *opexh, *opexl;
    bf16 *hbh, *hbl, *w1h, *w1l, *cwh, *cwl, *w2ihh, *w2ihl, *w2hhh, *w2hhl;
    float *c1, *gates, *last, *xp2, *h2, *c2, *cb, *gates2, *mu, *rs;
    double* bnacc;
    cudaGetSymbolAddress((void**)&condh, g_condh);
    cudaGetSymbolAddress((void**)&condl, g_condl);
    cudaGetSymbolAddress((void**)&h1h, g_h1h);
    cudaGetSymbolAddress((void**)&h1l, g_h1l);
    cudaGetSymbolAddress((void**)&c1, g_c1);
    cudaGetSymbolAddress((void**)&gates, g_gates);
    cudaGetSymbolAddress((void**)&last, g_last);
    cudaGetSymbolAddress((void**)&lasth, g_lasth);
    cudaGetSymbolAddress((void**)&lastl, g_lastl);
    cudaGetSymbolAddress((void**)&opexh, g_opexh);
    cudaGetSymbolAddress((void**)&opexl, g_opexl);
    cudaGetSymbolAddress((void**)&xp2, g_xp2);
    cudaGetSymbolAddress((void**)&h2, g_h2);
    cudaGetSymbolAddress((void**)&c2, g_c2);
    cudaGetSymbolAddress((void**)&hbh, g_hbh);
    cudaGetSymbolAddress((void**)&hbl, g_hbl);
    cudaGetSymbolAddress((void**)&cb, g_cb);
    cudaGetSymbolAddress((void**)&gates2, g_gates2);
    cudaGetSymbolAddress((void**)&w1h, g_w1h);
    cudaGetSymbolAddress((void**)&w1l, g_w1l);
    cudaGetSymbolAddress((void**)&cwh, g_cwh);
    cudaGetSymbolAddress((void**)&cwl, g_cwl);
    cudaGetSymbolAddress((void**)&w2ihh, g_w2ih);
    cudaGetSymbolAddress((void**)&w2ihl, g_w2il);
    cudaGetSymbolAddress((void**)&w2hhh, g_w2hh);
    cudaGetSymbolAddress((void**)&w2hhl, g_w2hl);
    cudaGetSymbolAddress((void**)&bnacc, g_bnacc);
    cudaGetSymbolAddress((void**)&mu, g_mu);
    cudaGetSymbolAddress((void**)&rs, g_rs);

    // ---- one-time splits into bf16 hi/lo (with concatenation)
    {
        long t;
        t = (long)BB * 2048;   // conditions [B][T*COND]
        split_k<<<(unsigned)((t + 255) / 256), 256>>>(conds, 2048, 2048, condh, condl, 2048, 0, t);
        t = (long)FOURH * CONDD; // w1 = [W1ih | W1hh]
        split_k<<<(unsigned)((t + 255) / 256), 256>>>(w1ih, CONDD, CONDD, w1h, w1l, 768, 0, t);
        t = (long)FOURH * HID;
        split_k<<<(unsigned)((t + 255) / 256), 256>>>(w1hh, HID, HID, w1h, w1l, 768, CONDD, t);
        t = (long)MID * HID;
        split_k<<<(unsigned)((t + 255) / 256), 256>>>(condW, HID, HID, cwh, cwl, HID, 0, t);
        t = (long)FOURH * 320;
        split_k<<<(unsigned)((t + 255) / 256), 256>>>(w2ih, 320, 320, w2ihh, w2ihl, 320, 0, t);
        t = (long)FOURH * HID;
        split_k<<<(unsigned)((t + 255) / 256), 256>>>(w2hh, HID, HID, w2hhh, w2hhl, HID, 0, t);
        t = (long)BB * OPD;    // opex = [op | extra]
        split_k<<<(unsigned)((t + 255) / 256), 256>>>(operators, OPD, OPD, opexh, opexl, 64, 0, t);
        split_k<<<(unsigned)((t + 255) / 256), 256>>>(extras, EXD, EXD, opexh, opexl, 64, OPD, t);
    }

    cudaMemsetAsync(h1h, 0, sizeof(bf16) * (size_t)BB * HID);
    cudaMemsetAsync(h1l, 0, sizeof(bf16) * (size_t)BB * HID);
    cudaMemsetAsync(c1, 0, sizeof(float) * (size_t)BB * HID);
    detect_k<<<1, 32>>>((const int*)mapping);

    // ---- lstm1: gates = [x_t | h] @ [W1ih | W1hh]^T + b1ih + b1hh
    for (int t = 0; t < TT; t++) {
        gemm_tc<0><<<dim3(FOURH/128, BB/128), 256, SMEM_TOT>>>(
            condh + t*CONDD, condl + t*CONDD, 2048, CONDD,
            h1h, h1l, HID,
            w1h, w1l, b1ih, b1hh, (const float*)0,
            gates, FOURH, CONDD + HID);
        cell1_k<<<(BB*HID)/256, 256>>>(gates, c1, h1h, h1l, c1);
    }

    // ---- last = relu(h1 @ condW^T + condb); batchnorm1 -> bf16 split
    gemm_tc<1><<<dim3(MID/128, BB/128), 256, SMEM_TOT>>>(
        h1h, h1l, HID, 1 << 30, h1h, h1l, HID,
        cwh, cwl, condb, (const float*)0, (const float*)0,
        last, MID, HID);
    cudaMemsetAsync(bnacc, 0, sizeof(double) * 2 * MID);
    bn_part_k<<<64, 256>>>(last, BB, MID, bnacc);
    bn_fin_k<<<2, 256>>>(bnacc, BB, MID, mu, rs);
    bn_apply_split_k<<<(BB*MID)/256, 256>>>(last, mu, rs, bn1g, bn1b, lasth, lastl, BB, MID);

    // ---- xp2 = [op|extra|last] @ W2ih^T + b2ih
    gemm_tc<2><<<dim3(FOURH/128, BB/128), 256, SMEM_TOT>>>(
        opexh, opexl, 64, 64,
        lasth, lastl, MID,
        w2ihh, w2ihl, b2ih, (const float*)0, (const float*)0,
        xp2, FOURH, 320);

    // ---- tree LSTM
    tcell0_k<<<(NN*HID)/256, 256>>>(xp2 + (long)(LLV-1)*NN*FOURH, b2hh, h2, c2);
    for (int lvl = LLV - 2; lvl >= 0; lvl--) {
        gatherT_k<<<(NN*HID)/256, 256>>>(mapping, lvl, h2, c2, hbh, hbl, cb);
        gemm_tc<3><<<dim3(FOURH/128, NN/128), 256, SMEM_TOT>>>(
            hbh, hbl, HID, 1 << 30, hbh, hbl, HID,
            w2hhh, w2hhl, b2hh, (const float*)0, xp2 + (long)lvl*NN*FOURH,
            gates2, FOURH, HID);
        cellT_k<<<(NN*HID)/256, 256>>>(gates2, cb, h2, c2);
    }

    // ---- batchnorm2 -> out
    cudaMemsetAsync(bnacc, 0, sizeof(double) * 2 * HID);
    bn_part_k<<<16, 256>>>(h2, NN, HID, bnacc);
    bn_fin_k<<<2, 256>>>(bnacc, NN, HID, mu, rs);
    bn_apply_k<<<(NN*HID)/256, 256>>>(h2, mu, rs, bn2g, bn2b, out, NN, HID);
}

// round 5
// speedup vs baseline: 3.3454x; 2.3644x over previous
#include <cuda_runtime.h>
#include <cuda_fp16.h>
#include <math.h>
#include <stdint.h>

typedef unsigned long long ull;

#define HID   512
#define FOURH 2048
#define MID   256
#define CONDD 256
#define OPD   32
#define EXD   32
#define LLV   16
#define NN    1024
#define TT    8
#define BB    (LLV*NN)   /* 16384 */

// ---------------------------------------------------------------- scratch ---
__device__ __align__(16) __half g_cond16[(size_t)BB*2048];
__device__ __align__(16) __half g_h1a[(size_t)BB*HID];
__device__ __align__(16) __half g_h1b[(size_t)BB*HID];
__device__ __align__(16) float  g_c1[(size_t)BB*HID];
__device__ __align__(16) float  g_last[(size_t)BB*MID];
__device__ __align__(16) __half g_last16[(size_t)BB*MID];
__device__ __align__(16) __half g_opex16[(size_t)BB*64];
__device__ __align__(16) float  g_xp2[(size_t)BB*FOURH];
__device__ __align__(16) float  g_h2[NN*HID];
__device__ __align__(16) float  g_c2[NN*HID];
__device__ __align__(16) __half g_hb16[NN*HID];
__device__ __align__(16) float  g_cb[NN*HID];
__device__ __align__(16) __half g_w1h[FOURH*768];
__device__ __align__(16) __half g_w1l[FOURH*768];
__device__ __align__(16) __half g_cwh[MID*HID];
__device__ __align__(16) __half g_cwl[MID*HID];
__device__ __align__(16) __half g_w2ih[FOURH*320];
__device__ __align__(16) __half g_w2il[FOURH*320];
__device__ __align__(16) __half g_w2hh[FOURH*HID];
__device__ __align__(16) __half g_w2hl[FOURH*HID];
__device__ double g_bnacc[2*HID];
__device__ float  g_mu[HID];
__device__ float  g_rs[HID];
__device__ int    g_map64;

// ---------------------------------------------------------------- helpers ---
__device__ __forceinline__ uint32_t smem_u32(const void* p) {
    uint32_t a;
    asm("{ .reg .u64 t; cvta.to.shared.u64 t, %1; cvt.u32.u64 %0, t; }" : "=r"(a) : "l"(p));
    return a;
}
__device__ __forceinline__ void cpa16(uint32_t dst, const void* src) {
    asm volatile("cp.async.cg.shared.global [%0], [%1], 16;" :: "r"(dst), "l"(src) : "memory");
}
__device__ __forceinline__ void ldmx4(uint32_t* r, uint32_t addr) {
    asm volatile("ldmatrix.sync.aligned.m8n8.x4.shared.b16 {%0,%1,%2,%3}, [%4];"
        : "=r"(r[0]), "=r"(r[1]), "=r"(r[2]), "=r"(r[3]) : "r"(addr));
}
__device__ __forceinline__ void mma_f16(float* d, const uint32_t* a, const uint32_t* b) {
    asm volatile("mma.sync.aligned.m16n8k16.row.col.f32.f16.f16.f32 "
        "{%0,%1,%2,%3}, {%4,%5,%6,%7}, {%8,%9}, {%0,%1,%2,%3};"
        : "+f"(d[0]), "+f"(d[1]), "+f"(d[2]), "+f"(d[3])
        : "r"(a[0]), "r"(a[1]), "r"(a[2]), "r"(a[3]), "r"(b[0]), "r"(b[1]));
}
__device__ __forceinline__ float sigm(float x) { return 1.f / (1.f + expf(-x)); }

// ---------------------------------------------------------------- GEMM ------
// C[M,Nf] = A[M,K] @ B[Nf,K]^T, A single fp16, B split fp16 hi/lo (2 mma products).
// CTA 128x128, K-chunk 32, double-buffered cp.async, 80B-padded smem rows.
// MODE 0: fused LSTM cell (interleaved gates), c in-place, h->f16 out
// MODE 1: relu(+bias0) -> f32 C
// MODE 2: +bias0 (perm-indexed, interleaved C) -> f32 C
// MODE 3: fused LSTM cell + Cadd(xp2), c: cIn2->cIO, h->f32 out
#define T_BH 10240
#define T_BL 20480
#define STAGE 30720
#define SMEM_TOT (2*STAGE)

template<int MODE>
__global__ __launch_bounds__(256, 2)
void gemm_k(const __half* __restrict__ A0, long sA0, int kSplit,
            const __half* __restrict__ A1, long sA1,
            const __half* __restrict__ Bh, const __half* __restrict__ Bl,
            const float* __restrict__ bias0, const float* __restrict__ bias1,
            const float* __restrict__ Cadd,
            float* __restrict__ cIO, const float* __restrict__ cIn2,
            __half* __restrict__ hOutH, float* __restrict__ hOutF,
            int Nf, int K)
{
    extern __shared__ __align__(128) char sm[];
    uint32_t smb = smem_u32(sm);
    int tid = threadIdx.x;
    int mBase = blockIdx.y * 128;
    int nBase = blockIdx.x * 128;

    float acc[4][4][4];
#pragma unroll
    for (int a = 0; a < 4; a++)
#pragma unroll
        for (int b = 0; b < 4; b++)
#pragma unroll
            for (int q = 0; q < 4; q++) acc[a][b][q] = 0.f;

    int NC = K >> 5;

    auto issue_stage = [&](int s, int c) {
        int kc = c << 5;
        const __half* ap; long sA; int col;
        if (kc < kSplit) { ap = A0; sA = sA0; col = kc; }
        else             { ap = A1; sA = sA1; col = kc - kSplit; }
        uint32_t stg = smb + (uint32_t)s * STAGE;
#pragma unroll
        for (int i = 0; i < 2; i++) {
            int idx = tid + (i << 8);
            int row = idx >> 2, cc = idx & 3;
            long eo = (long)(mBase + row) * sA + col + (cc << 3);
            cpa16(stg + row * 80 + cc * 16, ap + eo);
        }
#pragma unroll
        for (int i = 0; i < 2; i++) {
            int idx = tid + (i << 8);
            int row = idx >> 2, cc = idx & 3;
            long eo = (long)(nBase + row) * (long)K + kc + (cc << 3);
            uint32_t d = stg + row * 80 + cc * 16;
            cpa16(d + T_BH, Bh + eo);
            cpa16(d + T_BL, Bl + eo);
        }
        asm volatile("cp.async.commit_group;" ::: "memory");
    };

    int lane = tid & 31, wid = tid >> 5;
    int wm = wid & 1, wn = wid >> 1;
    int arow = (lane & 7) + (((lane >> 3) & 1) << 3);
    int ahalf = lane >> 4;
    int brow = ((lane >> 4) << 3) + (lane & 7);
    int bhalf = (lane >> 3) & 1;

    issue_stage(0, 0);
    for (int c = 0; c < NC; c++) {
        if (c + 1 < NC) {
            issue_stage((c + 1) & 1, c + 1);
            asm volatile("cp.async.wait_group 1;" ::: "memory");
        } else {
            asm volatile("cp.async.wait_group 0;" ::: "memory");
        }
        __syncthreads();

        uint32_t sb = smb + (uint32_t)(c & 1) * STAGE;
#pragma unroll
        for (int ks = 0; ks < 2; ks++) {
            uint32_t a_r[4][4], b_h[4][2], b_l[4][2];
#pragma unroll
            for (int mt = 0; mt < 4; mt++) {
                uint32_t ad = sb + (uint32_t)(wm * 64 + mt * 16 + arow) * 80
                            + (uint32_t)(ks * 2 + ahalf) * 16;
                ldmx4(a_r[mt], ad);
            }
#pragma unroll
            for (int bp = 0; bp < 2; bp++) {
                uint32_t bd = sb + T_BH + (uint32_t)(wn * 32 + bp * 16 + brow) * 80
                            + (uint32_t)(ks * 2 + bhalf) * 16;
                ldmx4(&b_h[bp * 2][0], bd);
                ldmx4(&b_l[bp * 2][0], bd + (T_BL - T_BH));
            }
#pragma unroll
            for (int mt = 0; mt < 4; mt++)
#pragma unroll
                for (int nt = 0; nt < 4; nt++) {
                    mma_f16(acc[mt][nt], a_r[mt], b_h[nt]);
                    mma_f16(acc[mt][nt], a_r[mt], b_l[nt]);
                }
        }
        __syncthreads();
    }

    // ---- epilogue
    if (MODE == 1 || MODE == 2) {
        int r4 = lane >> 2, c2 = (lane & 3) << 1;
#pragma unroll
        for (int mt = 0; mt < 4; mt++) {
            long m0 = mBase + wm * 64 + mt * 16 + r4;
#pragma unroll
            for (int nt = 0; nt < 4; nt++) {
                int gn = nBase + wn * 32 + nt * 8 + c2;
                int bx = (MODE == 2) ? ((gn & 3) * 512 + (gn >> 2)) : gn;
                int by = (MODE == 2) ? (((gn + 1) & 3) * 512 + ((gn + 1) >> 2)) : gn + 1;
                float b0x = bias0[bx], b0y = bias0[by];
#pragma unroll
                for (int hf = 0; hf < 2; hf++) {
                    long gm = m0 + hf * 8;
                    float vx = acc[mt][nt][hf * 2 + 0] + b0x;
                    float vy = acc[mt][nt][hf * 2 + 1] + b0y;
                    if (MODE == 1) { vx = fmaxf(vx, 0.f); vy = fmaxf(vy, 0.f); }
                    float2 v; v.x = vx; v.y = vy;
                    *(float2*)&hOutF[gm * (long)Nf + gn] = v;
                }
            }
        }
    } else {
        int half = lane & 1, r4 = lane >> 2;
#pragma unroll
        for (int nt = 0; nt < 4; nt++) {
            int j = (nBase + wn * 32 + nt * 8 + ((lane & 2) << 1)) >> 2;
            float bi = bias0[j], bf = bias0[512 + j], bg = bias0[1024 + j], bo = bias0[1536 + j];
            if (MODE == 0) {
                bi += bias1[j]; bf += bias1[512 + j];
                bg += bias1[1024 + j]; bo += bias1[1536 + j];
            }
#pragma unroll
            for (int mt = 0; mt < 4; mt++) {
                float v0 = acc[mt][nt][0], v1 = acc[mt][nt][1];
                float v2 = acc[mt][nt][2], v3 = acc[mt][nt][3];
                float p0 = __shfl_xor_sync(0xFFFFFFFFu, v0, 1);
                float p1 = __shfl_xor_sync(0xFFFFFFFFu, v1, 1);
                float p2 = __shfl_xor_sync(0xFFFFFFFFu, v2, 1);
                float p3 = __shfl_xor_sync(0xFFFFFFFFu, v3, 1);
                float gi, gf, gg, go;
                if (!half) { gi = v0; gf = v1; gg = p0; go = p1; }
                else       { gi = p2; gf = p3; gg = v2; go = v3; }
                long m = mBase + wm * 64 + mt * 16 + r4 + (half ? 8 : 0);
                if (MODE == 3) {
                    float4 xq = *(const float4*)&Cadd[m * (long)FOURH + 4 * (long)j];
                    gi += xq.x; gf += xq.y; gg += xq.z; go += xq.w;
                }
                gi += bi; gf += bf; gg += bg; go += bo;
                float cin = (MODE == 0) ? cIO[m * HID + j] : cIn2[m * HID + j];
                float cc = sigm(gf) * cin + sigm(gi) * tanhf(gg);
                float h = sigm(go) * tanhf(cc);
                cIO[m * HID + j] = cc;
                if (MODE == 0) hOutH[m * HID + j] = __float2half(h);
                else           hOutF[m * HID + j] = h;
            }
        }
    }
}

// ----------------------------------------------------------- converts -------
__global__ void cvt_k(const float* __restrict__ src, long sStr, int cols,
                      __half* __restrict__ dst, long dStr, int dOff, long total)
{
    long idx = (long)blockIdx.x * blockDim.x + threadIdx.x;
    if (idx >= total) return;
    long r = idx / cols; int c = (int)(idx - r * cols);
    dst[r * dStr + dOff + c] = __float2half(src[r * sStr + c]);
}

__global__ void splitW_k(const float* __restrict__ src, int cols,
                         __half* __restrict__ dh, __half* __restrict__ dl,
                         int dStr, int dOff, int interleave, long total)
{
    long idx = (long)blockIdx.x * blockDim.x + threadIdx.x;
    if (idx >= total) return;
    long r = idx / cols; int c = (int)(idx - r * cols);
    long dr = interleave ? (((r & 511) << 2) + (r >> 9)) : r;
    float v = src[r * cols + c];
    __half h = __float2half(v);
    __half l = __float2half(v - __half2float(h));
    dh[dr * dStr + dOff + c] = h;
    dl[dr * dStr + dOff + c] = l;
}

// ----------------------------------------------------------- elementwise ----
__global__ void tcell0_k(const float* __restrict__ xpl, const float* __restrict__ bhh,
                         float* __restrict__ h, float* __restrict__ c)
{
    int idx = blockIdx.x * blockDim.x + threadIdx.x;  // NN*HID
    int m = idx >> 9, j = idx & 511;
    float4 q = *(const float4*)&xpl[(long)m * FOURH + 4 * j];  // interleaved i,f,g,o
    float i_ = sigm(q.x + bhh[j]);
    float gg = tanhf(q.z + bhh[1024 + j]);
    float o_ = sigm(q.w + bhh[1536 + j]);
    float cc = i_ * gg;
    c[idx] = cc;
    h[idx] = o_ * tanhf(cc);
}

__global__ void detect_k(const int* __restrict__ m32)
{
    if (threadIdx.x == 0 && blockIdx.x == 0) {
        int all0 = 1;
        for (int i = 1; i < 64; i += 2) all0 &= (m32[i] == 0);
        g_map64 = all0;
    }
}

__global__ void gatherT_k(const void* __restrict__ mapping, int level,
                          const float* __restrict__ h, const float* __restrict__ c,
                          __half* __restrict__ hb, float* __restrict__ cb)
{
    int idx = blockIdx.x * blockDim.x + threadIdx.x;  // NN*HID
    int n = idx >> 9, j = idx & 511;
    long flat = ((long)level * NN + n) * 2;
    int m0, m1;
    if (g_map64) {
        m0 = (int)((const long long*)mapping)[flat];
        m1 = (int)((const long long*)mapping)[flat + 1];
    } else {
        m0 = ((const int*)mapping)[flat];
        m1 = ((const int*)mapping)[flat + 1];
    }
    float hv = 0.f, cv = 0.f;
    if (m0 > 0) { hv += h[(long)(m0-1)*HID + j]; cv += c[(long)(m0-1)*HID + j]; }
    if (m1 > 0) { hv += h[(long)(m1-1)*HID + j]; cv += c[(long)(m1-1)*HID + j]; }
    hb[idx] = __float2half(0.5f * hv);
    cb[idx] = 0.5f * cv;
}

// ---------------------------------------------------------------- batchnorm -
__global__ void bn_part_k(const float* __restrict__ x, int M, int N, double* __restrict__ acc)
{
    int rows = (M + gridDim.x - 1) / gridDim.x;
    int r0 = blockIdx.x * rows;
    int r1 = min(M, r0 + rows);
    for (int col = threadIdx.x; col < N; col += blockDim.x) {
        double s = 0.0, s2 = 0.0;
        for (int r = r0; r < r1; r++) {
            float v = x[(long)r * N + col];
            s += v; s2 += (double)v * v;
        }
        atomicAdd(&acc[col], s);
        atomicAdd(&acc[N + col], s2);
    }
}

__global__ void bn_fin_k(const double* __restrict__ acc, int M, int N,
                         float* __restrict__ mu, float* __restrict__ rs)
{
    int j = blockIdx.x * blockDim.x + threadIdx.x;
    if (j < N) {
        double m = acc[j] / M;
        double var = acc[N + j] / M - m * m;
        mu[j] = (float)m;
        rs[j] = rsqrtf((float)var + 1e-5f);
    }
}

__global__ void bn_apply_h_k(const float* __restrict__ x, const float* __restrict__ mu,
                             const float* __restrict__ rs, const float* __restrict__ gm_,
                             const float* __restrict__ bt, __half* __restrict__ y, int M, int N)
{
    long idx = (long)blockIdx.x * blockDim.x + threadIdx.x;
    if (idx < (long)M * N) {
        int j = idx % N;
        y[idx] = __float2half(gm_[j] * (x[idx] - mu[j]) * rs[j] + bt[j]);
    }
}

__global__ void bn_apply_k(const float* __restrict__ x, const float* __restrict__ mu,
                           const float* __restrict__ rs, const float* __restrict__ gm_,
                           const float* __restrict__ bt, float* __restrict__ y, int M, int N)
{
    int idx = blockIdx.x * blockDim.x + threadIdx.x;
    if (idx < M * N) {
        int j = idx % N;
        y[idx] = gm_[j] * (x[idx] - mu[j]) * rs[j] + bt[j];
    }
}

// ------------------------------------------------------------ orchestration -
extern "C" void kernel_launch(void* const* d_in, const int* in_sizes, int n_in,
                              void* d_out, int out_size)
{
    const float* operators = (const float*)d_in[0];
    const float* extras    = (const float*)d_in[1];
    const float* conds     = (const float*)d_in[2];
    const void*  mapping   =               d_in[4];
    const float* w1ih = (const float*)d_in[5];
    const float* w1hh = (const float*)d_in[6];
    const float* b1ih = (const float*)d_in[7];
    const float* b1hh = (const float*)d_in[8];
    const float* condW = (const float*)d_in[9];
    const float* condb = (const float*)d_in[10];
    const float* bn1g = (const float*)d_in[11];
    const float* bn1b = (const float*)d_in[12];
    const float* w2ih = (const float*)d_in[13];
    const float* w2hh = (const float*)d_in[14];
    const float* b2ih = (const float*)d_in[15];
    const float* b2hh = (const float*)d_in[16];
    const float* bn2g = (const float*)d_in[17];
    const float* bn2b = (const float*)d_in[18];
    float* out = (float*)d_out;

    cudaFuncSetAttribute(gemm_k<0>, cudaFuncAttributeMaxDynamicSharedMemorySize, SMEM_TOT);
    cudaFuncSetAttribute(gemm_k<1>, cudaFuncAttributeMaxDynamicSharedMemorySize, SMEM_TOT);
    cudaFuncSetAttribute(gemm_k<2>, cudaFuncAttributeMaxDynamicSharedMemorySize, SMEM_TOT);
    cudaFuncSetAttribute(gemm_k<3>, cudaFuncAttributeMaxDynamicSharedMemorySize, SMEM_TOT);

    __half *cond16, *h1a, *h1b, *last16, *opex16, *hb16;
    __half *w1h, *w1l, *cwh, *cwl, *w2ihh, *w2ihl, *w2hhh, *w2hhl;
    float *c1, *last, *xp2, *h2, *c2, *cb, *mu, *rs;
    double* bnacc;
    cudaGetSymbolAddress((void**)&cond16, g_cond16);
    cudaGetSymbolAddress((void**)&h1a, g_h1a);
    cudaGetSymbolAddress((void**)&h1b, g_h1b);
    cudaGetSymbolAddress((void**)&c1, g_c1);
    cudaGetSymbolAddress((void**)&last, g_last);
    cudaGetSymbolAddress((void**)&last16, g_last16);
    cudaGetSymbolAddress((void**)&opex16, g_opex16);
    cudaGetSymbolAddress((void**)&xp2, g_xp2);
    cudaGetSymbolAddress((void**)&h2, g_h2);
    cudaGetSymbolAddress((void**)&c2, g_c2);
    cudaGetSymbolAddress((void**)&hb16, g_hb16);
    cudaGetSymbolAddress((void**)&cb, g_cb);
    cudaGetSymbolAddress((void**)&w1h, g_w1h);
    cudaGetSymbolAddress((void**)&w1l, g_w1l);
    cudaGetSymbolAddress((void**)&cwh, g_cwh);
    cudaGetSymbolAddress((void**)&cwl, g_cwl);
    cudaGetSymbolAddress((void**)&w2ihh, g_w2ih);
    cudaGetSymbolAddress((void**)&w2ihl, g_w2il);
    cudaGetSymbolAddress((void**)&w2hhh, g_w2hh);
    cudaGetSymbolAddress((void**)&w2hhl, g_w2hl);
    cudaGetSymbolAddress((void**)&bnacc, g_bnacc);
    cudaGetSymbolAddress((void**)&mu, g_mu);
    cudaGetSymbolAddress((void**)&rs, g_rs);

    // ---- one-time converts / weight splits (interleaved gate rows for cell fusion)
    {
        long t;
        t = (long)BB * 2048;
        cvt_k<<<(unsigned)((t + 255) / 256), 256>>>(conds, 2048, 2048, cond16, 2048, 0, t);
        t = (long)FOURH * CONDD;
        splitW_k<<<(unsigned)((t + 255) / 256), 256>>>(w1ih, CONDD, w1h, w1l, 768, 0, 1, t);
        t = (long)FOURH * HID;
        splitW_k<<<(unsigned)((t + 255) / 256), 256>>>(w1hh, HID, w1h, w1l, 768, CONDD, 1, t);
        t = (long)MID * HID;
        splitW_k<<<(unsigned)((t + 255) / 256), 256>>>(condW, HID, cwh, cwl, HID, 0, 0, t);
        t = (long)FOURH * 320;
        splitW_k<<<(unsigned)((t + 255) / 256), 256>>>(w2ih, 320, w2ihh, w2ihl, 320, 0, 1, t);
        t = (long)FOURH * HID;
        splitW_k<<<(unsigned)((t + 255) / 256), 256>>>(w2hh, HID, w2hhh, w2hhl, HID, 0, 1, t);
        t = (long)BB * OPD;
        cvt_k<<<(unsigned)((t + 255) / 256), 256>>>(operators, OPD, OPD, opex16, 64, 0, t);
        cvt_k<<<(unsigned)((t + 255) / 256), 256>>>(extras, EXD, EXD, opex16, 64, OPD, t);
    }

    cudaMemsetAsync(h1a, 0, sizeof(__half) * (size_t)BB * HID);
    cudaMemsetAsync(c1, 0, sizeof(float) * (size_t)BB * HID);
    detect_k<<<1, 32>>>((const int*)mapping);

    // ---- lstm1: fused GEMM+cell, h ping-pong, c in place
    __half* hcur = h1a;
    __half* hnxt = h1b;
    for (int t = 0; t < TT; t++) {
        gemm_k<0><<<dim3(FOURH/128, BB/128), 256, SMEM_TOT>>>(
            cond16 + t*CONDD, 2048, CONDD,
            hcur, HID,
            w1h, w1l, b1ih, b1hh, (const float*)0,
            c1, (const float*)0, hnxt, (float*)0,
            FOURH, CONDD + HID);
        __half* tmp = hcur; hcur = hnxt; hnxt = tmp;
    }

    // ---- last = relu(h1 @ condW^T + condb); batchnorm1 -> f16
    gemm_k<1><<<dim3(MID/128, BB/128), 256, SMEM_TOT>>>(
        hcur, HID, 1 << 30, hcur, HID,
        cwh, cwl, condb, (const float*)0, (const float*)0,
        (float*)0, (const float*)0, (__half*)0, last,
        MID, HID);
    cudaMemsetAsync(bnacc, 0, sizeof(double) * 2 * MID);
    bn_part_k<<<128, 256>>>(last, BB, MID, bnacc);
    bn_fin_k<<<2, 256>>>(bnacc, BB, MID, mu, rs);
    bn_apply_h_k<<<(BB*MID)/256, 256>>>(last, mu, rs, bn1g, bn1b, last16, BB, MID);

    // ---- xp2 = [op|extra|last] @ W2ih^T + b2ih  (interleaved output)
    gemm_k<2><<<dim3(FOURH/128, BB/128), 256, SMEM_TOT>>>(
        opex16, 64, 64,
        last16, MID,
        w2ihh, w2ihl, b2ih, (const float*)0, (const float*)0,
        (float*)0, (const float*)0, (__half*)0, xp2,
        FOURH, 320);

    // ---- tree LSTM
    tcell0_k<<<(NN*HID)/256, 256>>>(xp2 + (long)(LLV-1)*NN*FOURH, b2hh, h2, c2);
    for (int lvl = LLV - 2; lvl >= 0; lvl--) {
        gatherT_k<<<(NN*HID)/256, 256>>>(mapping, lvl, h2, c2, hb16, cb);
        gemm_k<3><<<dim3(FOURH/128, NN/128), 256, SMEM_TOT>>>(
            hb16, HID, 1 << 30, hb16, HID,
            w2hhh, w2hhl, b2hh, (const float*)0, xp2 + (long)lvl*NN*FOURH,
            c2, cb, (__half*)0, h2,
            FOURH, HID);
    }

    // ---- batchnorm2 -> out
    cudaMemsetAsync(bnacc, 0, sizeof(double) * 2 * HID);
    bn_part_k<<<16, 256>>>(h2, NN, HID, bnacc);
    bn_fin_k<<<2, 256>>>(bnacc, NN, HID, mu, rs);
    bn_apply_k<<<(NN*HID)/256, 256>>>(h2, mu, rs, bn2g, bn2b, out, NN, HID);
}

// round 9
// speedup vs baseline: 3.6807x; 1.1002x over previous
#include <cuda_runtime.h>
#include <cuda_fp16.h>
#include <math.h>
#include <stdint.h>

typedef unsigned long long ull;

#define HID   512
#define FOURH 2048
#define MID   256
#define CONDD 256
#define OPD   32
#define EXD   32
#define LLV   16
#define NN    1024
#define TT    8
#define BB    (LLV*NN)   /* 16384 */

// ---------------------------------------------------------------- scratch ---
__device__ __align__(16) __half g_cond16[(size_t)BB*2048];
__device__ __align__(16) __half g_h1a[(size_t)BB*HID];
__device__ __align__(16) __half g_h1b[(size_t)BB*HID];
__device__ __align__(16) float  g_c1[(size_t)BB*HID];
__device__ __align__(16) float  g_last[(size_t)BB*MID];
__device__ __align__(16) __half g_last16[(size_t)BB*MID];
__device__ __align__(16) __half g_opex16[(size_t)BB*64];
__device__ __align__(16) float  g_xp2[(size_t)BB*FOURH];
__device__ __align__(16) float  g_h2[NN*HID];
__device__ __align__(16) float  g_c2[NN*HID];
__device__ __align__(16) __half g_hb16[NN*HID];
__device__ __align__(16) float  g_cb[NN*HID];
__device__ __align__(16) __half g_w1h[FOURH*768];
__device__ __align__(16) __half g_w1l[FOURH*768];
__device__ __align__(16) __half g_cwh[MID*HID];
__device__ __align__(16) __half g_cwl[MID*HID];
__device__ __align__(16) __half g_w2ih[FOURH*320];
__device__ __align__(16) __half g_w2il[FOURH*320];
__device__ __align__(16) __half g_w2hh[FOURH*HID];
__device__ __align__(16) __half g_w2hl[FOURH*HID];
__device__ double g_bnacc[2*HID];
__device__ float  g_mu[HID];
__device__ float  g_rs[HID];
__device__ int    g_map64;

// ---------------------------------------------------------------- helpers ---
__device__ __forceinline__ uint32_t smem_u32(const void* p) {
    uint32_t a;
    asm("{ .reg .u64 t; cvta.to.shared.u64 t, %1; cvt.u32.u64 %0, t; }" : "=r"(a) : "l"(p));
    return a;
}
__device__ __forceinline__ void cpa16(uint32_t dst, const void* src) {
    asm volatile("cp.async.cg.shared.global [%0], [%1], 16;" :: "r"(dst), "l"(src) : "memory");
}
__device__ __forceinline__ void ldmx4(uint32_t* r, uint32_t addr) {
    asm volatile("ldmatrix.sync.aligned.m8n8.x4.shared.b16 {%0,%1,%2,%3}, [%4];"
        : "=r"(r[0]), "=r"(r[1]), "=r"(r[2]), "=r"(r[3]) : "r"(addr));
}
__device__ __forceinline__ void mma_f16(float* d, const uint32_t* a, const uint32_t* b) {
    asm volatile("mma.sync.aligned.m16n8k16.row.col.f32.f16.f16.f32 "
        "{%0,%1,%2,%3}, {%4,%5,%6,%7}, {%8,%9}, {%0,%1,%2,%3};"
        : "+f"(d[0]), "+f"(d[1]), "+f"(d[2]), "+f"(d[3])
        : "r"(a[0]), "r"(a[1]), "r"(a[2]), "r"(a[3]), "r"(b[0]), "r"(b[1]));
}
__device__ __forceinline__ float sigm(float x) { return 1.f / (1.f + expf(-x)); }

// ---------------------------------------------------------------- GEMM ------
// C[M,Nf] = A[M,K] @ B[Nf,K]^T, A fp16, B fp16 hi (+ lo product only for
// K-chunks with kc >= loFrom — the recurrent-weight region).
// CTA 128x128, K-chunk 32, double-buffered cp.async, 80B-padded smem rows.
// MODE 0: fused LSTM cell (interleaved gates), c in-place, h->f16 out
// MODE 1: relu(+bias0) -> f32 C
// MODE 2: +bias0 (perm-indexed, interleaved C) -> f32 C
// MODE 3: fused LSTM cell + Cadd(xp2), c: cIn2->cIO, h->f32 out
#define T_BH 10240
#define T_BL 20480
#define STAGE 30720
#define SMEM_TOT (2*STAGE)

template<int MODE>
__global__ __launch_bounds__(256, 2)
void gemm_k(const __half* __restrict__ A0, long sA0, int kSplit,
            const __half* __restrict__ A1, long sA1,
            const __half* __restrict__ Bh, const __half* __restrict__ Bl,
            int loFrom,
            const float* __restrict__ bias0, const float* __restrict__ bias1,
            const float* __restrict__ Cadd,
            float* __restrict__ cIO, const float* __restrict__ cIn2,
            __half* __restrict__ hOutH, float* __restrict__ hOutF,
            int Nf, int K)
{
    extern __shared__ __align__(128) char sm[];
    uint32_t smb = smem_u32(sm);
    int tid = threadIdx.x;
    int mBase = blockIdx.y * 128;
    int nBase = blockIdx.x * 128;

    float acc[4][4][4];
#pragma unroll
    for (int a = 0; a < 4; a++)
#pragma unroll
        for (int b = 0; b < 4; b++)
#pragma unroll
            for (int q = 0; q < 4; q++) acc[a][b][q] = 0.f;

    int NC = K >> 5;

    auto issue_stage = [&](int s, int c) {
        int kc = c << 5;
        const __half* ap; long sA; int col;
        if (kc < kSplit) { ap = A0; sA = sA0; col = kc; }
        else             { ap = A1; sA = sA1; col = kc - kSplit; }
        uint32_t stg = smb + (uint32_t)s * STAGE;
#pragma unroll
        for (int i = 0; i < 2; i++) {
            int idx = tid + (i << 8);
            int row = idx >> 2, cc = idx & 3;
            long eo = (long)(mBase + row) * sA + col + (cc << 3);
            cpa16(stg + row * 80 + cc * 16, ap + eo);
        }
        int lo = (kc >= loFrom);
#pragma unroll
        for (int i = 0; i < 2; i++) {
            int idx = tid + (i << 8);
            int row = idx >> 2, cc = idx & 3;
            long eo = (long)(nBase + row) * (long)K + kc + (cc << 3);
            uint32_t d = stg + row * 80 + cc * 16;
            cpa16(d + T_BH, Bh + eo);
            if (lo) cpa16(d + T_BL, Bl + eo);
        }
        asm volatile("cp.async.commit_group;" ::: "memory");
    };

    int lane = tid & 31, wid = tid >> 5;
    int wm = wid & 1, wn = wid >> 1;
    int arow = (lane & 7) + (((lane >> 3) & 1) << 3);
    int ahalf = lane >> 4;
    int brow = ((lane >> 4) << 3) + (lane & 7);
    int bhalf = (lane >> 3) & 1;

    issue_stage(0, 0);
    for (int c = 0; c < NC; c++) {
        if (c + 1 < NC) {
            issue_stage((c + 1) & 1, c + 1);
            asm volatile("cp.async.wait_group 1;" ::: "memory");
        } else {
            asm volatile("cp.async.wait_group 0;" ::: "memory");
        }
        __syncthreads();

        uint32_t sb = smb + (uint32_t)(c & 1) * STAGE;
        int lo = ((c << 5) >= loFrom);
#pragma unroll
        for (int ks = 0; ks < 2; ks++) {
            uint32_t a_r[4][4], b_h[4][2], b_l[4][2];
#pragma unroll
            for (int mt = 0; mt < 4; mt++) {
                uint32_t ad = sb + (uint32_t)(wm * 64 + mt * 16 + arow) * 80
                            + (uint32_t)(ks * 2 + ahalf) * 16;
                ldmx4(a_r[mt], ad);
            }
#pragma unroll
            for (int bp = 0; bp < 2; bp++) {
                uint32_t bd = sb + T_BH + (uint32_t)(wn * 32 + bp * 16 + brow) * 80
                            + (uint32_t)(ks * 2 + bhalf) * 16;
                ldmx4(&b_h[bp * 2][0], bd);
                if (lo) ldmx4(&b_l[bp * 2][0], bd + (T_BL - T_BH));
            }
            if (lo) {
#pragma unroll
                for (int mt = 0; mt < 4; mt++)
#pragma unroll
                    for (int nt = 0; nt < 4; nt++) {
                        mma_f16(acc[mt][nt], a_r[mt], b_h[nt]);
                        mma_f16(acc[mt][nt], a_r[mt], b_l[nt]);
                    }
            } else {
#pragma unroll
                for (int mt = 0; mt < 4; mt++)
#pragma unroll
                    for (int nt = 0; nt < 4; nt++)
                        mma_f16(acc[mt][nt], a_r[mt], b_h[nt]);
            }
        }
        __syncthreads();
    }

    // ---- epilogue
    if (MODE == 1 || MODE == 2) {
        int r4 = lane >> 2, c2 = (lane & 3) << 1;
#pragma unroll
        for (int mt = 0; mt < 4; mt++) {
            long m0 = mBase + wm * 64 + mt * 16 + r4;
#pragma unroll
            for (int nt = 0; nt < 4; nt++) {
                int gn = nBase + wn * 32 + nt * 8 + c2;
                int bx = (MODE == 2) ? ((gn & 3) * 512 + (gn >> 2)) : gn;
                int by = (MODE == 2) ? (((gn + 1) & 3) * 512 + ((gn + 1) >> 2)) : gn + 1;
                float b0x = bias0[bx], b0y = bias0[by];
#pragma unroll
                for (int hf = 0; hf < 2; hf++) {
                    long gm = m0 + hf * 8;
                    float vx = acc[mt][nt][hf * 2 + 0] + b0x;
                    float vy = acc[mt][nt][hf * 2 + 1] + b0y;
                    if (MODE == 1) { vx = fmaxf(vx, 0.f); vy = fmaxf(vy, 0.f); }
                    float2 v; v.x = vx; v.y = vy;
                    *(float2*)&hOutF[gm * (long)Nf + gn] = v;
                }
            }
        }
    } else {
        int half = lane & 1, r4 = lane >> 2;
#pragma unroll
        for (int nt = 0; nt < 4; nt++) {
            int j = (nBase + wn * 32 + nt * 8 + ((lane & 2) << 1)) >> 2;
            float bi = bias0[j], bf = bias0[512 + j], bg = bias0[1024 + j], bo = bias0[1536 + j];
            if (MODE == 0) {
                bi += bias1[j]; bf += bias1[512 + j];
                bg += bias1[1024 + j]; bo += bias1[1536 + j];
            }
#pragma unroll
            for (int mt = 0; mt < 4; mt++) {
                float v0 = acc[mt][nt][0], v1 = acc[mt][nt][1];
                float v2 = acc[mt][nt][2], v3 = acc[mt][nt][3];
                float p0 = __shfl_xor_sync(0xFFFFFFFFu, v0, 1);
                float p1 = __shfl_xor_sync(0xFFFFFFFFu, v1, 1);
                float p2 = __shfl_xor_sync(0xFFFFFFFFu, v2, 1);
                float p3 = __shfl_xor_sync(0xFFFFFFFFu, v3, 1);
                float gi, gf, gg, go;
                if (!half) { gi = v0; gf = v1; gg = p0; go = p1; }
                else       { gi = p2; gf = p3; gg = v2; go = v3; }
                long m = mBase + wm * 64 + mt * 16 + r4 + (half ? 8 : 0);
                if (MODE == 3) {
                    float4 xq = *(const float4*)&Cadd[m * (long)FOURH + 4 * (long)j];
                    gi += xq.x; gf += xq.y; gg += xq.z; go += xq.w;
                }
                gi += bi; gf += bf; gg += bg; go += bo;
                float cin = (MODE == 0) ? cIO[m * HID + j] : cIn2[m * HID + j];
                float cc = sigm(gf) * cin + sigm(gi) * tanhf(gg);
                float h = sigm(go) * tanhf(cc);
                cIO[m * HID + j] = cc;
                if (MODE == 0) hOutH[m * HID + j] = __float2half(h);
                else           hOutF[m * HID + j] = h;
            }
        }
    }
}

// ----------------------------------------------------------- converts -------
__global__ void cvt_k(const float* __restrict__ src, long sStr, int cols,
                      __half* __restrict__ dst, long dStr, int dOff, long total)
{
    long idx = (long)blockIdx.x * blockDim.x + threadIdx.x;
    if (idx >= total) return;
    long r = idx / cols; int c = (int)(idx - r * cols);
    dst[r * dStr + dOff + c] = __float2half(src[r * sStr + c]);
}

__global__ void splitW_k(const float* __restrict__ src, int cols,
                         __half* __restrict__ dh, __half* __restrict__ dl,
                         int dStr, int dOff, int interleave, long total)
{
    long idx = (long)blockIdx.x * blockDim.x + threadIdx.x;
    if (idx >= total) return;
    long r = idx / cols; int c = (int)(idx - r * cols);
    long dr = interleave ? (((r & 511) << 2) + (r >> 9)) : r;
    float v = src[r * cols + c];
    __half h = __float2half(v);
    __half l = __float2half(v - __half2float(h));
    dh[dr * dStr + dOff + c] = h;
    dl[dr * dStr + dOff + c] = l;
}

__global__ void zero_k(__half* __restrict__ h, float* __restrict__ c, long n)
{
    long i = (long)blockIdx.x * blockDim.x + threadIdx.x;
    if (i < n) { h[i] = __float2half(0.f); c[i] = 0.f; }
}

// ----------------------------------------------------------- elementwise ----
__global__ void tcell0_k(const float* __restrict__ xpl, const float* __restrict__ bhh,
                         float* __restrict__ h, float* __restrict__ c)
{
    int idx = blockIdx.x * blockDim.x + threadIdx.x;  // NN*HID
    int m = idx >> 9, j = idx & 511;
    float4 q = *(const float4*)&xpl[(long)m * FOURH + 4 * j];  // interleaved i,f,g,o
    float i_ = sigm(q.x + bhh[j]);
    float gg = tanhf(q.z + bhh[1024 + j]);
    float o_ = sigm(q.w + bhh[1536 + j]);
    float cc = i_ * gg;
    c[idx] = cc;
    h[idx] = o_ * tanhf(cc);
}

__global__ void detect_k(const int* __restrict__ m32)
{
    if (threadIdx.x == 0 && blockIdx.x == 0) {
        int all0 = 1;
        for (int i = 1; i < 64; i += 2) all0 &= (m32[i] == 0);
        g_map64 = all0;
    }
}

__global__ void gatherT_k(const void* __restrict__ mapping, int level,
                          const float* __restrict__ h, const float* __restrict__ c,
                          __half* __restrict__ hb, float* __restrict__ cb)
{
    int idx = blockIdx.x * blockDim.x + threadIdx.x;  // NN*HID
    int n = idx >> 9, j = idx & 511;
    long flat = ((long)level * NN + n) * 2;
    int m0, m1;
    if (g_map64) {
        m0 = (int)((const long long*)mapping)[flat];
        m1 = (int)((const long long*)mapping)[flat + 1];
    } else {
        m0 = ((const int*)mapping)[flat];
        m1 = ((const int*)mapping)[flat + 1];
    }
    float hv = 0.f, cv = 0.f;
    if (m0 > 0) { hv += h[(long)(m0-1)*HID + j]; cv += c[(long)(m0-1)*HID + j]; }
    if (m1 > 0) { hv += h[(long)(m1-1)*HID + j]; cv += c[(long)(m1-1)*HID + j]; }
    hb[idx] = __float2half(0.5f * hv);
    cb[idx] = 0.5f * cv;
}

// ---------------------------------------------------------------- batchnorm -
__global__ void bn_part_k(const float* __restrict__ x, int M, int N, double* __restrict__ acc)
{
    int rows = (M + gridDim.x - 1) / gridDim.x;
    int r0 = blockIdx.x * rows;
    int r1 = min(M, r0 + rows);
    for (int col = threadIdx.x; col < N; col += blockDim.x) {
        double s = 0.0, s2 = 0.0;
        for (int r = r0; r < r1; r++) {
            float v = x[(long)r * N + col];
            s += v; s2 += (double)v * v;
        }
        atomicAdd(&acc[col], s);
        atomicAdd(&acc[N + col], s2);
    }
}

__global__ void bn_fin_k(const double* __restrict__ acc, int M, int N,
                         float* __restrict__ mu, float* __restrict__ rs)
{
    int j = blockIdx.x * blockDim.x + threadIdx.x;
    if (j < N) {
        double m = acc[j] / M;
        double var = acc[N + j] / M - m * m;
        mu[j] = (float)m;
        rs[j] = rsqrtf((float)var + 1e-5f);
    }
}

__global__ void bn_apply_h_k(const float* __restrict__ x, const float* __restrict__ mu,
                             const float* __restrict__ rs, const float* __restrict__ gm_,
                             const float* __restrict__ bt, __half* __restrict__ y, int M, int N)
{
    long idx = (long)blockIdx.x * blockDim.x + threadIdx.x;
    if (idx < (long)M * N) {
        int j = idx % N;
        y[idx] = __float2half(gm_[j] * (x[idx] - mu[j]) * rs[j] + bt[j]);
    }
}

__global__ void bn_apply_k(const float* __restrict__ x, const float* __restrict__ mu,
                           const float* __restrict__ rs, const float* __restrict__ gm_,
                           const float* __restrict__ bt, float* __restrict__ y, int M, int N)
{
    int idx = blockIdx.x * blockDim.x + threadIdx.x;
    if (idx < M * N) {
        int j = idx % N;
        y[idx] = gm_[j] * (x[idx] - mu[j]) * rs[j] + bt[j];
    }
}

// ------------------------------------------------------------ orchestration -
extern "C" void kernel_launch(void* const* d_in, const int* in_sizes, int n_in,
                              void* d_out, int out_size)
{
    const float* operators = (const float*)d_in[0];
    const float* extras    = (const float*)d_in[1];
    const float* conds     = (const float*)d_in[2];
    const void*  mapping   =               d_in[4];
    const float* w1ih = (const float*)d_in[5];
    const float* w1hh = (const float*)d_in[6];
    const float* b1ih = (const float*)d_in[7];
    const float* b1hh = (const float*)d_in[8];
    const float* condW = (const float*)d_in[9];
    const float* condb = (const float*)d_in[10];
    const float* bn1g = (const float*)d_in[11];
    const float* bn1b = (const float*)d_in[12];
    const float* w2ih = (const float*)d_in[13];
    const float* w2hh = (const float*)d_in[14];
    const float* b2ih = (const float*)d_in[15];
    const float* b2hh = (const float*)d_in[16];
    const float* bn2g = (const float*)d_in[17];
    const float* bn2b = (const float*)d_in[18];
    float* out = (float*)d_out;

    cudaFuncSetAttribute(gemm_k<0>, cudaFuncAttributeMaxDynamicSharedMemorySize, SMEM_TOT);
    cudaFuncSetAttribute(gemm_k<1>, cudaFuncAttributeMaxDynamicSharedMemorySize, SMEM_TOT);
    cudaFuncSetAttribute(gemm_k<2>, cudaFuncAttributeMaxDynamicSharedMemorySize, SMEM_TOT);
    cudaFuncSetAttribute(gemm_k<3>, cudaFuncAttributeMaxDynamicSharedMemorySize, SMEM_TOT);

    __half *cond16, *h1a, *h1b, *last16, *opex16, *hb16;
    __half *w1h, *w1l, *cwh, *cwl, *w2ihh, *w2ihl, *w2hhh, *w2hhl;
    float *c1, *last, *xp2, *h2, *c2, *cb, *mu, *rs;
    double* bnacc;
    cudaGetSymbolAddress((void**)&cond16, g_cond16);
    cudaGetSymbolAddress((void**)&h1a, g_h1a);
    cudaGetSymbolAddress((void**)&h1b, g_h1b);
    cudaGetSymbolAddress((void**)&c1, g_c1);
    cudaGetSymbolAddress((void**)&last, g_last);
    cudaGetSymbolAddress((void**)&last16, g_last16);
    cudaGetSymbolAddress((void**)&opex16, g_opex16);
    cudaGetSymbolAddress((void**)&xp2, g_xp2);
    cudaGetSymbolAddress((void**)&h2, g_h2);
    cudaGetSymbolAddress((void**)&c2, g_c2);
    cudaGetSymbolAddress((void**)&hb16, g_hb16);
    cudaGetSymbolAddress((void**)&cb, g_cb);
    cudaGetSymbolAddress((void**)&w1h, g_w1h);
    cudaGetSymbolAddress((void**)&w1l, g_w1l);
    cudaGetSymbolAddress((void**)&cwh, g_cwh);
    cudaGetSymbolAddress((void**)&cwl, g_cwl);
    cudaGetSymbolAddress((void**)&w2ihh, g_w2ih);
    cudaGetSymbolAddress((void**)&w2ihl, g_w2il);
    cudaGetSymbolAddress((void**)&w2hhh, g_w2hh);
    cudaGetSymbolAddress((void**)&w2hhl, g_w2hl);
    cudaGetSymbolAddress((void**)&bnacc, g_bnacc);
    cudaGetSymbolAddress((void**)&mu, g_mu);
    cudaGetSymbolAddress((void**)&rs, g_rs);

    // ---- launches 1-5 (so that launch #6 = gemm_k<0> for ncu -s 5 -c 1)
    {
        long t;
        t = (long)BB * 2048;                                                  // 1
        cvt_k<<<(unsigned)((t + 255) / 256), 256>>>(conds, 2048, 2048, cond16, 2048, 0, t);
        t = (long)FOURH * CONDD;                                              // 2
        splitW_k<<<(unsigned)((t + 255) / 256), 256>>>(w1ih, CONDD, w1h, w1l, 768, 0, 1, t);
        t = (long)FOURH * HID;                                                // 3
        splitW_k<<<(unsigned)((t + 255) / 256), 256>>>(w1hh, HID, w1h, w1l, 768, CONDD, 1, t);
        detect_k<<<1, 32>>>((const int*)mapping);                             // 4
        long n = (long)BB * HID;                                              // 5
        zero_k<<<(unsigned)((n + 255) / 256), 256>>>(h1a, c1, n);
    }

    // ---- lstm1: fused GEMM+cell, h ping-pong, c in place.
    // x-part (K<256) single product; W1hh region (K>=256) split hi+lo.
    __half* hcur = h1a;
    __half* hnxt = h1b;
    for (int t = 0; t < TT; t++) {
        gemm_k<0><<<dim3(FOURH/128, BB/128), 256, SMEM_TOT>>>(         // 6 = first
            cond16 + t*CONDD, 2048, CONDD,
            hcur, HID,
            w1h, w1l, CONDD,
            b1ih, b1hh, (const float*)0,
            c1, (const float*)0, hnxt, (float*)0,
            FOURH, CONDD + HID);
        __half* tmp = hcur; hcur = hnxt; hnxt = tmp;
    }

    // ---- remaining one-time weight converts (one-shot weights: single product)
    {
        long t;
        t = (long)MID * HID;
        splitW_k<<<(unsigned)((t + 255) / 256), 256>>>(condW, HID, cwh, cwl, HID, 0, 0, t);
        t = (long)FOURH * 320;
        splitW_k<<<(unsigned)((t + 255) / 256), 256>>>(w2ih, 320, w2ihh, w2ihl, 320, 0, 1, t);
        t = (long)FOURH * HID;
        splitW_k<<<(unsigned)((t + 255) / 256), 256>>>(w2hh, HID, w2hhh, w2hhl, HID, 0, 1, t);
        t = (long)BB * OPD;
        cvt_k<<<(unsigned)((t + 255) / 256), 256>>>(operators, OPD, OPD, opex16, 64, 0, t);
        cvt_k<<<(unsigned)((t + 255) / 256), 256>>>(extras, EXD, EXD, opex16, 64, OPD, t);
    }

    // ---- last = relu(h1 @ condW^T + condb); batchnorm1 -> f16  (single product)
    gemm_k<1><<<dim3(MID/128, BB/128), 256, SMEM_TOT>>>(
        hcur, HID, 1 << 30, hcur, HID,
        cwh, cwl, 1 << 30,
        condb, (const float*)0, (const float*)0,
        (float*)0, (const float*)0, (__half*)0, last,
        MID, HID);
    cudaMemsetAsync(bnacc, 0, sizeof(double) * 2 * MID);
    bn_part_k<<<128, 256>>>(last, BB, MID, bnacc);
    bn_fin_k<<<2, 256>>>(bnacc, BB, MID, mu, rs);
    bn_apply_h_k<<<(BB*MID)/256, 256>>>(last, mu, rs, bn1g, bn1b, last16, BB, MID);

    // ---- xp2 = [op|extra|last] @ W2ih^T + b2ih  (interleaved output, single product)
    gemm_k<2><<<dim3(FOURH/128, BB/128), 256, SMEM_TOT>>>(
        opex16, 64, 64,
        last16, MID,
        w2ihh, w2ihl, 1 << 30,
        b2ih, (const float*)0, (const float*)0,
        (float*)0, (const float*)0, (__half*)0, xp2,
        FOURH, 320);

    // ---- tree LSTM (recurrent W2hh: split hi+lo)
    tcell0_k<<<(NN*HID)/256, 256>>>(xp2 + (long)(LLV-1)*NN*FOURH, b2hh, h2, c2);
    for (int lvl = LLV - 2; lvl >= 0; lvl--) {
        gatherT_k<<<(NN*HID)/256, 256>>>(mapping, lvl, h2, c2, hb16, cb);
        gemm_k<3><<<dim3(FOURH/128, NN/128), 256, SMEM_TOT>>>(
            hb16, HID, 1 << 30, hb16, HID,
            w2hhh, w2hhl, 0,
            b2hh, (const float*)0, xp2 + (long)lvl*NN*FOURH,
            c2, cb, (__half*)0, h2,
            FOURH, HID);
    }

    // ---- batchnorm2 -> out
    cudaMemsetAsync(bnacc, 0, sizeof(double) * 2 * HID);
    bn_part_k<<<16, 256>>>(h2, NN, HID, bnacc);
    bn_fin_k<<<2, 256>>>(bnacc, NN, HID, mu, rs);
    bn_apply_k<<<(NN*HID)/256, 256>>>(h2, mu, rs, bn2g, bn2b, out, NN, HID);
}